// round 5
// baseline (speedup 1.0000x reference)
#include <cuda_runtime.h>
#include <math.h>

#define B_  32
#define N_  1024
#define CD_ 896
#define GD_ 384
#define HD_ 256
#define OD_ 1280

// ---------------- scratch (device globals; no allocation allowed) ------------
__device__ float g_Q[B_ * N_ * HD_];     // 32 MB
__device__ float g_K[B_ * N_ * HD_];     // 32 MB
__device__ float g_V[B_ * N_ * HD_];     // 32 MB
__device__ float g_att[B_ * N_ * HD_];   // 32 MB (attended)
__device__ float g_cpool[B_ * CD_];
__device__ float g_gpool[B_ * HD_];
__device__ float g_comb[B_ * OD_];
__device__ float g_h[B_ * OD_];

// ---------------- 128x128x8 SGEMM, 256 threads, 8x8 per thread ---------------
// EPI: 0 = +bias[n], 1 = *scale + logf(cw + 1e-8), 2 = none
// TRANSB: B is [N, Kd] row-major (NT GEMM, used for Q @ K^T)
template <bool TRANSB, int EPI>
__global__ __launch_bounds__(256) void sgemm128(
    const float* __restrict__ A, const float* __restrict__ Bm,
    const float* __restrict__ bias, const float* __restrict__ cw,
    float* __restrict__ C, int M, int Kd, int N,
    long sA, long sB, long sC, float scale)
{
    const int bz = blockIdx.z;
    A  += (long)bz * sA;
    Bm += (long)bz * sB;
    C  += (long)bz * sC;
    const long cwoff = (long)bz * (long)M * (long)N;

    __shared__ float As[8][128];
    __shared__ float Bs[8][128];

    const int tid = threadIdx.x;
    const int tx  = tid & 15;        // 0..15 -> 8 cols each
    const int ty  = tid >> 4;        // 0..15 -> 8 rows each
    const int bm  = blockIdx.x * 128;
    const int bn  = blockIdx.y * 128;
    const int lrow = tid >> 1;              // 0..127
    const int lk4  = (tid & 1) << 2;        // 0 or 4
    const int brow = tid >> 5;              // 0..7
    const int bcol = (tid & 31) << 2;       // 0..124

    float acc[8][8];
#pragma unroll
    for (int i = 0; i < 8; i++)
#pragma unroll
        for (int j = 0; j < 8; j++) acc[i][j] = 0.f;

    for (int k0 = 0; k0 < Kd; k0 += 8) {
        float4 av = *(const float4*)&A[(long)(bm + lrow) * Kd + k0 + lk4];
        As[lk4 + 0][lrow] = av.x;
        As[lk4 + 1][lrow] = av.y;
        As[lk4 + 2][lrow] = av.z;
        As[lk4 + 3][lrow] = av.w;
        if (TRANSB) {
            float4 bv = *(const float4*)&Bm[(long)(bn + lrow) * Kd + k0 + lk4];
            Bs[lk4 + 0][lrow] = bv.x;
            Bs[lk4 + 1][lrow] = bv.y;
            Bs[lk4 + 2][lrow] = bv.z;
            Bs[lk4 + 3][lrow] = bv.w;
        } else {
            *(float4*)&Bs[brow][bcol] =
                *(const float4*)&Bm[(long)(k0 + brow) * N + bn + bcol];
        }
        __syncthreads();
#pragma unroll
        for (int kk = 0; kk < 8; kk++) {
            float a[8], b[8];
            *(float4*)&a[0] = *(const float4*)&As[kk][ty * 8];
            *(float4*)&a[4] = *(const float4*)&As[kk][ty * 8 + 4];
            *(float4*)&b[0] = *(const float4*)&Bs[kk][tx * 8];
            *(float4*)&b[4] = *(const float4*)&Bs[kk][tx * 8 + 4];
#pragma unroll
            for (int i = 0; i < 8; i++)
#pragma unroll
                for (int j = 0; j < 8; j++)
                    acc[i][j] = fmaf(a[i], b[j], acc[i][j]);
        }
        __syncthreads();
    }

#pragma unroll
    for (int i = 0; i < 8; i++) {
        const int m = bm + ty * 8 + i;
#pragma unroll
        for (int j = 0; j < 8; j++) {
            const int n = bn + tx * 8 + j;
            float v = acc[i][j];
            if (EPI == 0) {
                v += bias[n];
            } else if (EPI == 1) {
                v = v * scale + logf(cw[cwoff + (long)m * N + n] + 1e-8f);
            }
            C[(long)m * N + n] = v;
        }
    }
}

// ---------------- row softmax over N=1024, one block per row -----------------
__global__ __launch_bounds__(256) void softmax1024(float* __restrict__ S)
{
    float4* row = (float4*)(S + (long)blockIdx.x * N_);
    const int tid = threadIdx.x;
    float4 v = row[tid];

    float m = fmaxf(fmaxf(v.x, v.y), fmaxf(v.z, v.w));
#pragma unroll
    for (int o = 16; o > 0; o >>= 1)
        m = fmaxf(m, __shfl_xor_sync(0xffffffffu, m, o));
    __shared__ float redm[8];
    if ((tid & 31) == 0) redm[tid >> 5] = m;
    __syncthreads();
    m = fmaxf(fmaxf(fmaxf(redm[0], redm[1]), fmaxf(redm[2], redm[3])),
              fmaxf(fmaxf(redm[4], redm[5]), fmaxf(redm[6], redm[7])));

    v.x = __expf(v.x - m); v.y = __expf(v.y - m);
    v.z = __expf(v.z - m); v.w = __expf(v.w - m);
    float s = v.x + v.y + v.z + v.w;
#pragma unroll
    for (int o = 16; o > 0; o >>= 1)
        s += __shfl_xor_sync(0xffffffffu, s, o);
    __shared__ float reds[8];
    if ((tid & 31) == 0) reds[tid >> 5] = s;
    __syncthreads();
    s = (reds[0] + reds[1]) + (reds[2] + reds[3]) +
        (reds[4] + reds[5]) + (reds[6] + reds[7]);
    const float inv = 1.0f / s;
    v.x *= inv; v.y *= inv; v.z *= inv; v.w *= inv;
    row[tid] = v;
}

// ---------------- mean over N axis: X[B,N,D] -> out[B,D] ---------------------
__global__ __launch_bounds__(128) void pool_mean(const float* __restrict__ X,
                                                 float* __restrict__ out, int D)
{
    const int d = blockIdx.x * 128 + threadIdx.x;
    const float* p = X + (long)blockIdx.y * N_ * D + d;
    float s0 = 0.f, s1 = 0.f, s2 = 0.f, s3 = 0.f;
    for (int n = 0; n < N_; n += 4) {
        s0 += p[(long)(n + 0) * D];
        s1 += p[(long)(n + 1) * D];
        s2 += p[(long)(n + 2) * D];
        s3 += p[(long)(n + 3) * D];
    }
    out[blockIdx.y * D + d] = ((s0 + s1) + (s2 + s3)) * (1.0f / N_);
}

// ---------------- head: concat of two linears --------------------------------
__global__ __launch_bounds__(256) void head_combined(
    const float* __restrict__ cpool, const float* __restrict__ gpool,
    const float* __restrict__ Wcp, const float* __restrict__ bcp,
    const float* __restrict__ Wgp, const float* __restrict__ bgp,
    float* __restrict__ comb)
{
    const int b = blockIdx.y;
    const int o = blockIdx.x * 256 + threadIdx.x;
    float acc;
    if (o < OD_ / 2) {
        const float* a = cpool + b * CD_;
        acc = bcp[o];
        for (int k = 0; k < CD_; k++)
            acc = fmaf(a[k], Wcp[k * (OD_ / 2) + o], acc);
    } else {
        const int oo = o - OD_ / 2;
        const float* a = gpool + b * HD_;
        acc = bgp[oo];
        for (int k = 0; k < HD_; k++)
            acc = fmaf(a[k], Wgp[k * (OD_ / 2) + oo], acc);
    }
    comb[b * OD_ + o] = acc;
}

// ---------------- head: Linear -> BN(eval) -> ReLU ---------------------------
__global__ __launch_bounds__(256) void head_f1(
    const float* __restrict__ comb, const float* __restrict__ W,
    const float* __restrict__ bias, const float* __restrict__ gam,
    const float* __restrict__ bet, const float* __restrict__ mean,
    const float* __restrict__ var, float* __restrict__ h)
{
    __shared__ float sa[OD_];
    const int b = blockIdx.y;
    const int o = blockIdx.x * 256 + threadIdx.x;
    for (int i = threadIdx.x; i < OD_; i += 256) sa[i] = comb[b * OD_ + i];
    __syncthreads();
    float acc = bias[o];
    for (int k = 0; k < OD_; k++)
        acc = fmaf(sa[k], W[(long)k * OD_ + o], acc);
    acc = (acc - mean[o]) * rsqrtf(var[o] + 1e-5f) * gam[o] + bet[o];
    h[b * OD_ + o] = fmaxf(acc, 0.f);
}

// ---------------- head: final Linear -----------------------------------------
__global__ __launch_bounds__(256) void head_f2(
    const float* __restrict__ h, const float* __restrict__ W,
    const float* __restrict__ bias, float* __restrict__ out)
{
    __shared__ float sa[OD_];
    const int b = blockIdx.y;
    const int o = blockIdx.x * 256 + threadIdx.x;
    for (int i = threadIdx.x; i < OD_; i += 256) sa[i] = h[b * OD_ + i];
    __syncthreads();
    float acc = bias[o];
    for (int k = 0; k < OD_; k++)
        acc = fmaf(sa[k], W[(long)k * OD_ + o], acc);
    out[b * OD_ + o] = acc;
}

// -----------------------------------------------------------------------------
extern "C" void kernel_launch(void* const* d_in, const int* in_sizes, int n_in,
                              void* d_out, int out_size)
{
    const float* cf  = (const float*)d_in[0];   // [B,N,CD]
    const float* gf  = (const float*)d_in[1];   // [B,N,GD]
    const float* cw  = (const float*)d_in[2];   // [B,N,N]
    const float* Wq  = (const float*)d_in[3];
    const float* bq  = (const float*)d_in[4];
    const float* Wk  = (const float*)d_in[5];
    const float* bk  = (const float*)d_in[6];
    const float* Wv  = (const float*)d_in[7];
    const float* bv  = (const float*)d_in[8];
    const float* Wcp = (const float*)d_in[9];
    const float* bcp = (const float*)d_in[10];
    const float* Wgp = (const float*)d_in[11];
    const float* bgp = (const float*)d_in[12];
    const float* Wf1 = (const float*)d_in[13];
    const float* bf1 = (const float*)d_in[14];
    const float* bng = (const float*)d_in[15];
    const float* bnb = (const float*)d_in[16];
    const float* bnm = (const float*)d_in[17];
    const float* bnv = (const float*)d_in[18];
    const float* Wf2 = (const float*)d_in[19];
    const float* bf2 = (const float*)d_in[20];

    float* out  = (float*)d_out;            // [B, OD]  = 40960 floats
    float* attn = out + B_ * OD_;           // [B, N, N]

    float *Q, *K, *V, *att, *cp, *gp, *comb, *h;
    cudaGetSymbolAddress((void**)&Q,    g_Q);
    cudaGetSymbolAddress((void**)&K,    g_K);
    cudaGetSymbolAddress((void**)&V,    g_V);
    cudaGetSymbolAddress((void**)&att,  g_att);
    cudaGetSymbolAddress((void**)&cp,   g_cpool);
    cudaGetSymbolAddress((void**)&gp,   g_gpool);
    cudaGetSymbolAddress((void**)&comb, g_comb);
    cudaGetSymbolAddress((void**)&h,    g_h);

    // Projections (flattened over B*N rows)
    sgemm128<false, 0><<<dim3(256, 2, 1), 256>>>(
        cf, Wq, bq, nullptr, Q, B_ * N_, CD_, HD_, 0, 0, 0, 0.f);
    sgemm128<false, 0><<<dim3(256, 2, 1), 256>>>(
        gf, Wk, bk, nullptr, K, B_ * N_, GD_, HD_, 0, 0, 0, 0.f);
    sgemm128<false, 0><<<dim3(256, 2, 1), 256>>>(
        gf, Wv, bv, nullptr, V, B_ * N_, GD_, HD_, 0, 0, 0, 0.f);

    // scores = Q K^T * (1/16) + log(cw + 1e-8)  -> attn region of d_out
    sgemm128<true, 1><<<dim3(8, 8, B_), 256>>>(
        Q, K, nullptr, cw, attn, N_, HD_, N_,
        (long)N_ * HD_, (long)N_ * HD_, (long)N_ * N_, 0.0625f);

    // softmax over last axis, in place
    softmax1024<<<B_ * N_, 256>>>(attn);

    // attended = attn @ V
    sgemm128<false, 2><<<dim3(8, 2, B_), 256>>>(
        attn, V, nullptr, nullptr, att, N_, N_, HD_,
        (long)N_ * N_, (long)N_ * HD_, (long)N_ * HD_, 0.f);

    // pooled means
    pool_mean<<<dim3(CD_ / 128, B_), 128>>>(cf, cp, CD_);
    pool_mean<<<dim3(HD_ / 128, B_), 128>>>(att, gp, HD_);

    // head
    head_combined<<<dim3(OD_ / 256, B_), 256>>>(cp, gp, Wcp, bcp, Wgp, bgp, comb);
    head_f1<<<dim3(OD_ / 256, B_), 256>>>(comb, Wf1, bf1, bng, bnb, bnm, bnv, h);
    head_f2<<<dim3(OD_ / 256, B_), 256>>>(h, Wf2, bf2, out);
}